// round 14
// baseline (speedup 1.0000x reference)
#include <cuda_runtime.h>

typedef unsigned long long u64;

// ---------------- problem constants ----------------
#define CC 8
#define KK 1024
#define THREADS 512
#define NBLOCKS 144            // 18 blocks per codebook, zero cb switches
#define BPC 18

// ---------------- smem layout (float offsets) ----------------
#define OFF_CB   0             // 32768: 1024 rows x 128B, SW128-swizzled
#define OFF_DS   32768         // 16384: 2 x [8 n][1024 k] dists (canonical)
#define OFF_ZFT  49152         // 512:   2 x [32 j][8 n]
#define OFF_ZFTT 49664         // 1320:  5 x [8 n][stride 33 j]
#define OFF_RED  50984         // 4096:  2 x [8 slab][8 n][32 j]
#define OFF_IDX  55080         // 24 ints (3 x 8)
#define OFF_FLG  55104         // 1
#define OFF_SCR  55108         // 16
#define SMEM_FLOATS 55124
#define SMEM_BYTES (SMEM_FLOATS * 4)   // 220496 B

// ---------------- output packing (float32, tuple order) ----------------
#define O_IDX   1048576u
#define O_Q     1081344u
#define O_SC    34635776u

// ---------------- global scratch ----------------
__device__ float g_qbar[CC * KK];
__device__ float g_comm;
__device__ float g_ne;
__device__ float g_qd;
__device__ unsigned int g_count;

// ---------------- f32x2 helpers ----------------
__device__ __forceinline__ void fma2(u64 &d, u64 a, u64 b) {
    asm("fma.rn.f32x2 %0, %1, %2, %0;" : "+l"(d) : "l"(a), "l"(b));
}
__device__ __forceinline__ u64 add2(u64 a, u64 b) {
    u64 r; asm("add.rn.f32x2 %0, %1, %2;" : "=l"(r) : "l"(a), "l"(b)); return r;
}
__device__ __forceinline__ u64 dup2(float x) {
    u64 r; asm("mov.b64 %0, {%1, %1};" : "=l"(r) : "f"(x)); return r;
}
__device__ __forceinline__ u64 pk2(float lo, float hi) {
    u64 r; asm("mov.b64 %0, {%1, %2};" : "=l"(r) : "f"(lo), "f"(hi)); return r;
}
__device__ __forceinline__ void unpk2(u64 v, float &lo, float &hi) {
    asm("mov.b64 {%0, %1}, %2;" : "=f"(lo), "=f"(hi) : "l"(v));
}
__device__ __forceinline__ u64 shfl_xor64(u64 v, int m) {
    return __shfl_xor_sync(0xffffffffu, v, m);
}

// ---------------- swizzled codebook addressing (128B rows, SW128) ----------
__device__ __forceinline__ const float4* cb_vec(const char* cbb, int k, int j4) {
    return (const float4*)(cbb + k * 128 + ((j4 * 16) ^ ((k & 7) << 4)));
}
__device__ __forceinline__ float cb_el(const char* cbb, int k, int j) {
    return *(const float*)(cbb + k * 128 + ((j * 4) ^ ((k & 7) << 4)));
}

__global__ void __launch_bounds__(THREADS, 1)
lgq_main(const float* __restrict__ z, const float* __restrict__ cbg,
         float* __restrict__ out)
{
    extern __shared__ float sm[];
    char*  cbb  = (char*)sm;
    float* ds   = sm + OFF_DS;
    float* zft  = sm + OFF_ZFT;
    float* zftT = sm + OFF_ZFTT;
    float* red  = sm + OFF_RED;
    int*   idxs = (int*)(sm + OFF_IDX);
    float* scr  = sm + OFF_SCR;

    const int t    = threadIdx.x;
    const int w    = t >> 5;
    const int lane = t & 31;
    const int bx   = blockIdx.x;

    const int c  = bx / BPC;
    const int bi = bx % BPC;
    const int s  = bi * 28 + min(bi, 8);
    const int e  = s + 28 + (bi < 8 ? 1 : 0);

    // ---- stage codebook c (swizzled) ----
    {
        const float4* cb4 = (const float4*)(cbg + (size_t)c * (KK * 32));
        #pragma unroll
        for (int it = 0; it < 16; it++) {
            int idx = t + it * THREADS;
            float4 v = cb4[idx];
            int k = idx >> 3, j4 = idx & 7;
            *(float4*)(cbb + k * 128 + ((j4 * 16) ^ ((k & 7) << 4))) = v;
        }
    }
    float zsq_acc = 0.0f;
    // ---- prestage zf(tile s) ----
    if (t < 256) {
        int jj0 = t >> 3, ni0 = t & 7;
        int n = s * 8 + ni0, b = n >> 10;
        float v = z[(size_t)(b * 256 + c * 32 + jj0) * 1024 + (n & 1023)];
        zft[(s & 1) * 256 + jj0 * 8 + ni0]   = v;
        zftT[(s % 5) * 264 + ni0 * 33 + jj0] = v;
        zsq_acc = v * v;
    }
    __syncthreads();

    // ---- codeword norms for k0 + 256m (p1 warps) ----
    const int k0 = t & 255;
    float cq[4];
    #pragma unroll
    for (int m = 0; m < 4; m++) {
        int k = k0 + 256 * m;
        float sq = 0.0f;
        #pragma unroll
        for (int j4 = 0; j4 < 8; j4++) {
            float4 v = *cb_vec(cbb, k, j4);
            sq += v.x * v.x + v.y * v.y + v.z * v.z + v.w * v.w;
        }
        cq[m] = sq;
    }

    float acc_ne = 0.0f, acc_qd = 0.0f, ct_comm = 0.0f;
    u64 qbs0 = 0ull, qbs1 = 0ull;      // qbar pairs for k = 4*t2 .. 4*t2+3
    const int t2 = t - 256;            // consumer-group thread id (w >= 8)

    // =====================================================================
    // ONE barrier per iteration. Iter i:
    //   P (w<8):  LDG zf(i+3) | p1(i+2)->ds[i&1] | quantized+indices(i-1) |
    //             STS zf(i+3)
    //   C (w>=8): p3(i) from GLOBAL q -> red[i%2] + qbar(i) |
    //             p2(i+1) (q -> GLOBAL, idxs) | commitment(i-1)
    // =====================================================================
    for (int i = s - 2; i <= e; i++) {
        if (w < 8) {
            // ---- LDG zf(i+3) ----
            float zn = 0.0f;
            const bool ldg_ok = (i + 3 < e);
            const int jj0 = t >> 3, ni0 = t & 7;
            if (ldg_ok) {
                int n = (i + 3) * 8 + ni0, b = n >> 10;
                zn = z[(size_t)(b * 256 + c * 32 + jj0) * 1024 + (n & 1023)];
            }

            // ---- p1(i+2): dists -> ds[i&1] ----
            if (i + 2 < e) {
                u64 acc[4][4];
                #pragma unroll
                for (int np = 0; np < 4; np++)
                    #pragma unroll
                    for (int m = 0; m < 4; m++) acc[np][m] = 0ull;

                const int sx = (k0 & 7) << 4;
                const float* zb = zft + ((i + 2) & 1) * 256;
                float* dsb = ds + (i & 1) * 8192;   // (i+2)&1 == i&1

                #pragma unroll
                for (int j4 = 0; j4 < 8; j4++) {
                    const int off = (j4 * 16) ^ sx;
                    float4 cv0 = *(const float4*)(cbb + k0 * 128 + off);
                    float4 cv1 = *(const float4*)(cbb + (k0 + 256) * 128 + off);
                    float4 cv2 = *(const float4*)(cbb + (k0 + 512) * 128 + off);
                    float4 cv3 = *(const float4*)(cbb + (k0 + 768) * 128 + off);
                    #pragma unroll
                    for (int eI = 0; eI < 4; eI++) {
                        const ulonglong2* zp =
                            (const ulonglong2*)(zb + (j4 * 4 + eI) * 8);
                        ulonglong2 zA = zp[0], zB = zp[1];
                        float e0 = (eI == 0) ? cv0.x : (eI == 1) ? cv0.y
                                 : (eI == 2) ? cv0.z : cv0.w;
                        float e1 = (eI == 0) ? cv1.x : (eI == 1) ? cv1.y
                                 : (eI == 2) ? cv1.z : cv1.w;
                        float e2 = (eI == 0) ? cv2.x : (eI == 1) ? cv2.y
                                 : (eI == 2) ? cv2.z : cv2.w;
                        float e3 = (eI == 0) ? cv3.x : (eI == 1) ? cv3.y
                                 : (eI == 2) ? cv3.z : cv3.w;
                        u64 d0 = dup2(e0), d1 = dup2(e1);
                        u64 d2 = dup2(e2), d3 = dup2(e3);
                        fma2(acc[0][0], zA.x, d0); fma2(acc[0][1], zA.x, d1);
                        fma2(acc[0][2], zA.x, d2); fma2(acc[0][3], zA.x, d3);
                        fma2(acc[1][0], zA.y, d0); fma2(acc[1][1], zA.y, d1);
                        fma2(acc[1][2], zA.y, d2); fma2(acc[1][3], zA.y, d3);
                        fma2(acc[2][0], zB.x, d0); fma2(acc[2][1], zB.x, d1);
                        fma2(acc[2][2], zB.x, d2); fma2(acc[2][3], zB.x, d3);
                        fma2(acc[3][0], zB.y, d0); fma2(acc[3][1], zB.y, d1);
                        fma2(acc[3][2], zB.y, d2); fma2(acc[3][3], zB.y, d3);
                    }
                }
                #pragma unroll
                for (int np = 0; np < 4; np++)
                    #pragma unroll
                    for (int m = 0; m < 4; m++) {
                        float a, b2; unpk2(acc[np][m], a, b2);
                        int k = k0 + 256 * m;
                        dsb[(2 * np) * 1024 + k]     = fmaf(-2.0f, a,  cq[m]);
                        dsb[(2 * np + 1) * 1024 + k] = fmaf(-2.0f, b2, cq[m]);
                    }
            }

            // ---- quantized + indices for tile (i-1) ----
            if (i >= s + 1) {
                const int ti = i - 1;
                {
                    int ni0 = t & 7, jq = t >> 3;
                    int n = ti * 8 + ni0, b = n >> 10;
                    int kq = idxs[(ti % 3) * 8 + ni0];
                    out[(size_t)(b * 256 + c * 32 + jq) * 1024 + (n & 1023)] =
                        cb_el(cbb, kq, jq);
                }
                if (t < 8) {
                    int n = ti * 8 + t, b = n >> 10;
                    out[O_IDX + (size_t)b * 8192 + c * 1024 + (n & 1023)] =
                        (float)idxs[(ti % 3) * 8 + t];
                }
            }

            // ---- STS zf(i+3) ----
            if (ldg_ok) {
                zft[((i + 3) & 1) * 256 + jj0 * 8 + ni0]   = zn;
                zftT[((i + 3) % 5) * 264 + ni0 * 33 + jj0] = zn;
                zsq_acc += zn * zn;
            }
        } else {
            // ===== C: p3(i) + qbar(i) from GLOBAL q =======================
            if (i >= s && i < e) {
                const int s3 = w - 8;
                const int ks = lane >> 3;
                const int jg = lane & 7;
                const float* gq = out + O_Q + (size_t)c * 1024
                                + (size_t)i * 8 * 8192;
                u64 acc[8][2];
                #pragma unroll
                for (int n2 = 0; n2 < 8; n2++) { acc[n2][0] = 0ull; acc[n2][1] = 0ull; }

                #pragma unroll
                for (int i4 = 0; i4 < 8; i4++) {
                    const int kb = s3 * 128 + ks * 32 + i4 * 4;
                    u64 cj0[4], cj1[4];
                    #pragma unroll
                    for (int eI = 0; eI < 4; eI++) {
                        const float4 v = *(const float4*)(cbb + (kb + eI) * 128 +
                            ((jg * 16) ^ (((kb + eI) & 7) << 4)));
                        cj0[eI] = pk2(v.x, v.y);
                        cj1[eI] = pk2(v.z, v.w);
                    }
                    #pragma unroll
                    for (int n2 = 0; n2 < 8; n2++) {
                        const float4 qv =
                            *(const float4*)(gq + (size_t)n2 * 8192 + kb);
                        u64 dx = dup2(qv.x), dy = dup2(qv.y);
                        u64 dz = dup2(qv.z), dw = dup2(qv.w);
                        fma2(acc[n2][0], dx, cj0[0]); fma2(acc[n2][1], dx, cj1[0]);
                        fma2(acc[n2][0], dy, cj0[1]); fma2(acc[n2][1], dy, cj1[1]);
                        fma2(acc[n2][0], dz, cj0[2]); fma2(acc[n2][1], dz, cj1[2]);
                        fma2(acc[n2][0], dw, cj0[3]); fma2(acc[n2][1], dw, cj1[3]);
                    }
                }
                #pragma unroll
                for (int n2 = 0; n2 < 8; n2++) {
                    acc[n2][0] = add2(acc[n2][0], shfl_xor64(acc[n2][0], 8));
                    acc[n2][1] = add2(acc[n2][1], shfl_xor64(acc[n2][1], 8));
                    acc[n2][0] = add2(acc[n2][0], shfl_xor64(acc[n2][0], 16));
                    acc[n2][1] = add2(acc[n2][1], shfl_xor64(acc[n2][1], 16));
                }
                u64 r0a = acc[0][0], r1a = acc[0][1];
                u64 r0b = acc[1][0], r1b = acc[1][1];
                if (ks == 1) { r0a = acc[2][0]; r1a = acc[2][1];
                               r0b = acc[3][0]; r1b = acc[3][1]; }
                if (ks == 2) { r0a = acc[4][0]; r1a = acc[4][1];
                               r0b = acc[5][0]; r1b = acc[5][1]; }
                if (ks == 3) { r0a = acc[6][0]; r1a = acc[6][1];
                               r0b = acc[7][0]; r1b = acc[7][1]; }
                float a0, a1, a2, a3;
                float* rd = red + (i & 1) * 2048;
                unpk2(r0a, a0, a1); unpk2(r1a, a2, a3);
                *(float4*)(rd + s3 * 256 + (ks * 2) * 32 + jg * 4) =
                    make_float4(a0, a1, a2, a3);
                unpk2(r0b, a0, a1); unpk2(r1b, a2, a3);
                *(float4*)(rd + s3 * 256 + (ks * 2 + 1) * 32 + jg * 4) =
                    make_float4(a0, a1, a2, a3);

                // vectorized qbar: thread owns k = 4*t2 .. 4*t2+3
                #pragma unroll
                for (int n2 = 0; n2 < 8; n2++) {
                    ulonglong2 qq =
                        *(const ulonglong2*)(gq + (size_t)n2 * 8192 + 4 * t2);
                    qbs0 = add2(qbs0, qq.x);
                    qbs1 = add2(qbs1, qq.y);
                }
            }

            // ---- p2(i+1): softmax/argmin row (w-8); q -> GLOBAL ----
            if (i + 1 >= s && i + 1 < e) {
                const int n2p = w - 8;
                const float* row = ds + ((i + 1) & 1) * 8192 + n2p * 1024;
                const float4* row4 = (const float4*)row;
                float dv[32];
                #pragma unroll
                for (int m4 = 0; m4 < 8; m4++) {
                    float4 v = row4[lane + 32 * m4];
                    dv[m4 * 4 + 0] = v.x; dv[m4 * 4 + 1] = v.y;
                    dv[m4 * 4 + 2] = v.z; dv[m4 * 4 + 3] = v.w;
                }
                float rmin = 3.4e38f; int kmin = 1 << 30;
                #pragma unroll
                for (int ii = 0; ii < 32; ii++) {
                    int k = 4 * lane + 128 * (ii >> 2) + (ii & 3);
                    float dd = dv[ii];
                    if (dd < rmin || (dd == rmin && k < kmin)) { rmin = dd; kmin = k; }
                }
                #pragma unroll
                for (int off = 16; off; off >>= 1) {
                    float od = __shfl_xor_sync(0xffffffffu, rmin, off);
                    int   ok = __shfl_xor_sync(0xffffffffu, kmin, off);
                    if (od < rmin || (od == rmin && ok < kmin)) { rmin = od; kmin = ok; }
                }
                float Z = 0.0f, sed = 0.0f;
                #pragma unroll
                for (int ii = 0; ii < 32; ii++) {
                    float told = dv[ii];
                    float ev = __expf((rmin - told) * 0.5f);
                    Z += ev;
                    sed = fmaf(ev, told, sed);
                    dv[ii] = ev;
                }
                #pragma unroll
                for (int off = 16; off; off >>= 1) {
                    Z   += __shfl_xor_sync(0xffffffffu, Z, off);
                    sed += __shfl_xor_sync(0xffffffffu, sed, off);
                }
                float rZ = __fdividef(1.0f, Z);
                float qd = sed * rZ;

                int n = (i + 1) * 8 + n2p;
                float4* gq4 = (float4*)(out + O_Q + ((size_t)n * 8 + c) * 1024);
                #pragma unroll
                for (int m4 = 0; m4 < 8; m4++) {
                    float4 qv;
                    qv.x = dv[m4 * 4 + 0] * rZ; qv.y = dv[m4 * 4 + 1] * rZ;
                    qv.z = dv[m4 * 4 + 2] * rZ; qv.w = dv[m4 * 4 + 3] * rZ;
                    gq4[lane + 32 * m4] = qv;
                }
                if (lane == 0) {
                    acc_ne += 0.5f * (rmin - qd) - __logf(Z);
                    acc_qd += qd;
                    idxs[((i + 1) % 3) * 8 + n2p] = kmin;
                }
            }

            // ---- commitment for tile (i-1) ----
            if (i >= s + 1) {
                const int ti = i - 1;
                int cn = t2 >> 5, cj = t2 & 31;
                const float* rd = red + (ti & 1) * 2048;
                float sr = 0.0f;
                #pragma unroll
                for (int ss = 0; ss < 8; ss++)
                    sr += rd[ss * 256 + cn * 32 + cj];
                float diff = zftT[(ti % 5) * 264 + cn * 33 + cj] - sr;
                ct_comm = fmaf(diff, diff, ct_comm);
            }
        }
        __syncthreads();
    }

    // ---- flush accumulators ----
    #pragma unroll
    for (int off = 16; off; off >>= 1) {
        ct_comm += __shfl_xor_sync(0xffffffffu, ct_comm, off);
        zsq_acc += __shfl_xor_sync(0xffffffffu, zsq_acc, off);
    }
    if (lane == 0) {
        atomicAdd(&g_comm, ct_comm);
        atomicAdd(&g_qd, zsq_acc + acc_qd);
        atomicAdd(&g_ne, acc_ne);
    }
    if (w >= 8) {
        float a, b2;
        unpk2(qbs0, a, b2);
        atomicAdd(&g_qbar[c * 1024 + 4 * t2 + 0], a);
        atomicAdd(&g_qbar[c * 1024 + 4 * t2 + 1], b2);
        unpk2(qbs1, a, b2);
        atomicAdd(&g_qbar[c * 1024 + 4 * t2 + 2], a);
        atomicAdd(&g_qbar[c * 1024 + 4 * t2 + 3], b2);
    }

    // ---- last-block finalize (ticket) ----
    __threadfence();
    int* flag = (int*)(sm + OFF_FLG);
    if (t == 0) {
        unsigned int v = atomicAdd(&g_count, 1u);
        flag[0] = (v == (unsigned)(NBLOCKS - 1));
    }
    __syncthreads();
    if (flag[0]) {
        float local = 0.0f;
        #pragma unroll
        for (int it = 0; it < 16; it++) {
            int idx = t + it * THREADS;
            float qb = g_qbar[idx] * (1.0f / 4096.0f);
            local += qb * __logf(fmaf(qb, 1024.0f, 1e-8f));
            g_qbar[idx] = 0.0f;                 // reset for next graph replay
        }
        #pragma unroll
        for (int off = 16; off; off >>= 1)
            local += __shfl_xor_sync(0xffffffffu, local, off);
        if (lane == 0) scr[w] = local;
        __syncthreads();
        if (t == 0) {
            float sr = 0.0f;
            #pragma unroll
            for (int ii = 0; ii < 16; ii++) sr += scr[ii];
            float balance = sr * 0.125f;
            float comm = g_comm * (1.0f / 1048576.0f);
            float mne  = g_ne   * (1.0f / 32768.0f);
            float mqd  = g_qd   * (1.0f / 32768.0f);
            out[O_SC + 0] = comm;
            out[O_SC + 1] = fmaf(mqd, 0.5f, mne) + 6.93147180559945f;
            out[O_SC + 2] = -mne;
            out[O_SC + 3] = balance;
            out[O_SC + 4] = 1.0f;
            g_comm = 0.0f; g_ne = 0.0f; g_qd = 0.0f;
            g_count = 0u;
        }
    }
}

extern "C" void kernel_launch(void* const* d_in, const int* in_sizes, int n_in,
                              void* d_out, int out_size)
{
    const float* z   = (const float*)d_in[0];   // (4,256,32,32) f32
    const float* cbg = (const float*)d_in[1];   // (8,1024,32)  f32
    float* out = (float*)d_out;

    cudaFuncSetAttribute(lgq_main, cudaFuncAttributeMaxDynamicSharedMemorySize,
                         SMEM_BYTES);
    lgq_main<<<NBLOCKS, THREADS, SMEM_BYTES>>>(z, cbg, out);
}

// round 15
// speedup vs baseline: 1.1038x; 1.1038x over previous
#include <cuda_runtime.h>

typedef unsigned long long u64;

// ---------------- problem constants ----------------
#define CC 8
#define KK 1024
#define THREADS 512
#define NBLOCKS 144            // 18 blocks per codebook, zero cb switches
#define BPC 18

// ---------------- smem layout (float offsets) ----------------
#define OFF_CB   0             // 32768: 1024 rows x 128B, SW128-swizzled
#define OFF_DS   32768         // 16384: 2 x [8 n][1024 k] dists (canonical)
#define OFF_ZFT  49152         // 512:   2 x [32 j][8 n]
#define OFF_ZFTT 49664         // 1320:  5 x [8 n][stride 33 j]
#define OFF_RED  50984         // 4096:  2 x [8 slab][8 n][32 j]
#define OFF_IDX  55080         // 24 ints (3 x 8)
#define OFF_FLG  55104         // 1
#define OFF_SCR  55108         // 16
#define SMEM_FLOATS 55124
#define SMEM_BYTES (SMEM_FLOATS * 4)   // 220496 B

// ---------------- output packing (float32, tuple order) ----------------
#define O_IDX   1048576u
#define O_Q     1081344u
#define O_SC    34635776u

// ---------------- global scratch ----------------
__device__ float g_qbar[CC * KK];
__device__ float g_comm;
__device__ float g_ne;
__device__ float g_qd;
__device__ unsigned int g_count;

// ---------------- f32x2 helpers ----------------
__device__ __forceinline__ void fma2(u64 &d, u64 a, u64 b) {
    asm("fma.rn.f32x2 %0, %1, %2, %0;" : "+l"(d) : "l"(a), "l"(b));
}
__device__ __forceinline__ u64 add2(u64 a, u64 b) {
    u64 r; asm("add.rn.f32x2 %0, %1, %2;" : "=l"(r) : "l"(a), "l"(b)); return r;
}
__device__ __forceinline__ u64 dup2(float x) {
    u64 r; asm("mov.b64 %0, {%1, %1};" : "=l"(r) : "f"(x)); return r;
}
__device__ __forceinline__ u64 pk2(float lo, float hi) {
    u64 r; asm("mov.b64 %0, {%1, %2};" : "=l"(r) : "f"(lo), "f"(hi)); return r;
}
__device__ __forceinline__ void unpk2(u64 v, float &lo, float &hi) {
    asm("mov.b64 {%0, %1}, %2;" : "=f"(lo), "=f"(hi) : "l"(v));
}
__device__ __forceinline__ u64 shfl_xor64(u64 v, int m) {
    return __shfl_xor_sync(0xffffffffu, v, m);
}

// ---------------- swizzled codebook addressing (128B rows, SW128) ----------
__device__ __forceinline__ const float4* cb_vec(const char* cbb, int k, int j4) {
    return (const float4*)(cbb + k * 128 + ((j4 * 16) ^ ((k & 7) << 4)));
}
__device__ __forceinline__ float cb_el(const char* cbb, int k, int j) {
    return *(const float*)(cbb + k * 128 + ((j * 4) ^ ((k & 7) << 4)));
}

__global__ void __launch_bounds__(THREADS, 1)
lgq_main(const float* __restrict__ z, const float* __restrict__ cbg,
         float* __restrict__ out)
{
    extern __shared__ float sm[];
    char*  cbb  = (char*)sm;
    float* ds   = sm + OFF_DS;
    float* zft  = sm + OFF_ZFT;
    float* zftT = sm + OFF_ZFTT;
    float* red  = sm + OFF_RED;
    int*   idxs = (int*)(sm + OFF_IDX);
    float* scr  = sm + OFF_SCR;

    const int t    = threadIdx.x;
    const int w    = t >> 5;
    const int lane = t & 31;
    const int bx   = blockIdx.x;

    const int c  = bx / BPC;
    const int bi = bx % BPC;
    const int s  = bi * 28 + min(bi, 8);
    const int e  = s + 28 + (bi < 8 ? 1 : 0);

    // ---- stage codebook c (swizzled) ----
    {
        const float4* cb4 = (const float4*)(cbg + (size_t)c * (KK * 32));
        #pragma unroll
        for (int it = 0; it < 16; it++) {
            int idx = t + it * THREADS;
            float4 v = cb4[idx];
            int k = idx >> 3, j4 = idx & 7;
            *(float4*)(cbb + k * 128 + ((j4 * 16) ^ ((k & 7) << 4))) = v;
        }
    }
    float zsq_acc = 0.0f;
    // ---- prestage zf(tile s) ----
    if (t < 256) {
        int jj0 = t >> 3, ni0 = t & 7;
        int n = s * 8 + ni0, b = n >> 10;
        float v = z[(size_t)(b * 256 + c * 32 + jj0) * 1024 + (n & 1023)];
        zft[(s & 1) * 256 + jj0 * 8 + ni0]   = v;
        zftT[(s % 5) * 264 + ni0 * 33 + jj0] = v;
        zsq_acc = v * v;
    }
    __syncthreads();

    // ---- codeword norms for k0 + 256m (p1 warps) ----
    const int k0 = t & 255;
    float cq[4];
    #pragma unroll
    for (int m = 0; m < 4; m++) {
        int k = k0 + 256 * m;
        float sq = 0.0f;
        #pragma unroll
        for (int j4 = 0; j4 < 8; j4++) {
            float4 v = *cb_vec(cbb, k, j4);
            sq += v.x * v.x + v.y * v.y + v.z * v.z + v.w * v.w;
        }
        cq[m] = sq;
    }

    float acc_ne = 0.0f, acc_qd = 0.0f, ct_comm = 0.0f;
    u64 qbs0 = 0ull, qbs1 = 0ull;      // qbar pairs for k = 4*t2 .. 4*t2+3
    const int t2 = t - 256;            // consumer-group thread id (w >= 8)

    // =====================================================================
    // ONE barrier per iteration. Iter i:
    //   P (w<8):  LDG zf(i+3) | p1(i+2)->ds[i&1] | p2(i+1) (q -> GLOBAL) |
    //             commitment(i-1) | STS zf(i+3)
    //   C (w>=8): p3(i) from GLOBAL q -> red[i%2] | qbar(i) vectorized |
    //             quantized+indices(i-1)
    // =====================================================================
    for (int i = s - 2; i <= e; i++) {
        if (w < 8) {
            // ---- LDG zf(i+3) ----
            float zn = 0.0f;
            const bool ldg_ok = (i + 3 < e);
            const int jj0 = t >> 3, ni0 = t & 7;
            if (ldg_ok) {
                int n = (i + 3) * 8 + ni0, b = n >> 10;
                zn = z[(size_t)(b * 256 + c * 32 + jj0) * 1024 + (n & 1023)];
            }

            // ---- p1(i+2): dists -> ds[i&1] ----
            if (i + 2 < e) {
                u64 acc[4][4];
                #pragma unroll
                for (int np = 0; np < 4; np++)
                    #pragma unroll
                    for (int m = 0; m < 4; m++) acc[np][m] = 0ull;

                const int sx = (k0 & 7) << 4;
                const float* zb = zft + ((i + 2) & 1) * 256;
                float* dsb = ds + (i & 1) * 8192;   // (i+2)&1 == i&1

                #pragma unroll
                for (int j4 = 0; j4 < 8; j4++) {
                    const int off = (j4 * 16) ^ sx;
                    float4 cv0 = *(const float4*)(cbb + k0 * 128 + off);
                    float4 cv1 = *(const float4*)(cbb + (k0 + 256) * 128 + off);
                    float4 cv2 = *(const float4*)(cbb + (k0 + 512) * 128 + off);
                    float4 cv3 = *(const float4*)(cbb + (k0 + 768) * 128 + off);
                    #pragma unroll
                    for (int eI = 0; eI < 4; eI++) {
                        const ulonglong2* zp =
                            (const ulonglong2*)(zb + (j4 * 4 + eI) * 8);
                        ulonglong2 zA = zp[0], zB = zp[1];
                        float e0 = (eI == 0) ? cv0.x : (eI == 1) ? cv0.y
                                 : (eI == 2) ? cv0.z : cv0.w;
                        float e1 = (eI == 0) ? cv1.x : (eI == 1) ? cv1.y
                                 : (eI == 2) ? cv1.z : cv1.w;
                        float e2 = (eI == 0) ? cv2.x : (eI == 1) ? cv2.y
                                 : (eI == 2) ? cv2.z : cv2.w;
                        float e3 = (eI == 0) ? cv3.x : (eI == 1) ? cv3.y
                                 : (eI == 2) ? cv3.z : cv3.w;
                        u64 d0 = dup2(e0), d1 = dup2(e1);
                        u64 d2 = dup2(e2), d3 = dup2(e3);
                        fma2(acc[0][0], zA.x, d0); fma2(acc[0][1], zA.x, d1);
                        fma2(acc[0][2], zA.x, d2); fma2(acc[0][3], zA.x, d3);
                        fma2(acc[1][0], zA.y, d0); fma2(acc[1][1], zA.y, d1);
                        fma2(acc[1][2], zA.y, d2); fma2(acc[1][3], zA.y, d3);
                        fma2(acc[2][0], zB.x, d0); fma2(acc[2][1], zB.x, d1);
                        fma2(acc[2][2], zB.x, d2); fma2(acc[2][3], zB.x, d3);
                        fma2(acc[3][0], zB.y, d0); fma2(acc[3][1], zB.y, d1);
                        fma2(acc[3][2], zB.y, d2); fma2(acc[3][3], zB.y, d3);
                    }
                }
                #pragma unroll
                for (int np = 0; np < 4; np++)
                    #pragma unroll
                    for (int m = 0; m < 4; m++) {
                        float a, b2; unpk2(acc[np][m], a, b2);
                        int k = k0 + 256 * m;    // canonical layout
                        dsb[(2 * np) * 1024 + k]     = fmaf(-2.0f, a,  cq[m]);
                        dsb[(2 * np + 1) * 1024 + k] = fmaf(-2.0f, b2, cq[m]);
                    }
            }

            // ---- p2(i+1): softmax/argmin row w; q -> GLOBAL only ----
            if (i + 1 >= s && i + 1 < e) {
                const float* row = ds + ((i + 1) & 1) * 8192 + w * 1024;
                const float4* row4 = (const float4*)row;
                float dv[32];
                #pragma unroll
                for (int m4 = 0; m4 < 8; m4++) {
                    float4 v = row4[lane + 32 * m4];
                    dv[m4 * 4 + 0] = v.x; dv[m4 * 4 + 1] = v.y;
                    dv[m4 * 4 + 2] = v.z; dv[m4 * 4 + 3] = v.w;
                }
                float rmin = 3.4e38f; int kmin = 1 << 30;
                #pragma unroll
                for (int ii = 0; ii < 32; ii++) {
                    int k = 4 * lane + 128 * (ii >> 2) + (ii & 3);
                    float dd = dv[ii];
                    if (dd < rmin || (dd == rmin && k < kmin)) { rmin = dd; kmin = k; }
                }
                #pragma unroll
                for (int off = 16; off; off >>= 1) {
                    float od = __shfl_xor_sync(0xffffffffu, rmin, off);
                    int   ok = __shfl_xor_sync(0xffffffffu, kmin, off);
                    if (od < rmin || (od == rmin && ok < kmin)) { rmin = od; kmin = ok; }
                }
                float Z = 0.0f, sed = 0.0f;
                #pragma unroll
                for (int ii = 0; ii < 32; ii++) {
                    float told = dv[ii];
                    float ev = __expf((rmin - told) * 0.5f);
                    Z += ev;
                    sed = fmaf(ev, told, sed);
                    dv[ii] = ev;
                }
                #pragma unroll
                for (int off = 16; off; off >>= 1) {
                    Z   += __shfl_xor_sync(0xffffffffu, Z, off);
                    sed += __shfl_xor_sync(0xffffffffu, sed, off);
                }
                float rZ = __fdividef(1.0f, Z);
                float qd = sed * rZ;

                int n = (i + 1) * 8 + w;
                float4* gq4 = (float4*)(out + O_Q + ((size_t)n * 8 + c) * 1024);
                #pragma unroll
                for (int m4 = 0; m4 < 8; m4++) {
                    float4 qv;
                    qv.x = dv[m4 * 4 + 0] * rZ; qv.y = dv[m4 * 4 + 1] * rZ;
                    qv.z = dv[m4 * 4 + 2] * rZ; qv.w = dv[m4 * 4 + 3] * rZ;
                    gq4[lane + 32 * m4] = qv;
                }
                if (lane == 0) {
                    acc_ne += 0.5f * (rmin - qd) - __logf(Z);
                    acc_qd += qd;
                    idxs[((i + 1) % 3) * 8 + w] = kmin;
                }
            }

            // ---- commitment for tile (i-1) ----
            if (i >= s + 1 && t < 256) {
                const int ti = i - 1;
                int cn = t >> 5, cj = t & 31;
                const float* rd = red + (ti & 1) * 2048;
                float sr = 0.0f;
                #pragma unroll
                for (int ss = 0; ss < 8; ss++)
                    sr += rd[ss * 256 + cn * 32 + cj];
                float diff = zftT[(ti % 5) * 264 + cn * 33 + cj] - sr;
                ct_comm = fmaf(diff, diff, ct_comm);
            }

            // ---- STS zf(i+3) ----
            if (ldg_ok) {
                zft[((i + 3) & 1) * 256 + jj0 * 8 + ni0]   = zn;
                zftT[((i + 3) % 5) * 264 + ni0 * 33 + jj0] = zn;
                zsq_acc += zn * zn;
            }
        } else {
            // ===== C: p3(i) + vectorized qbar(i) from GLOBAL q ============
            if (i >= s && i < e) {
                const int s3 = w - 8;
                const int ks = lane >> 3;
                const int jg = lane & 7;
                const float* gq = out + O_Q + (size_t)c * 1024
                                + (size_t)i * 8 * 8192;
                u64 acc[8][2];
                #pragma unroll
                for (int n2 = 0; n2 < 8; n2++) { acc[n2][0] = 0ull; acc[n2][1] = 0ull; }

                #pragma unroll
                for (int i4 = 0; i4 < 8; i4++) {
                    const int kb = s3 * 128 + ks * 32 + i4 * 4;
                    u64 cj0[4], cj1[4];
                    #pragma unroll
                    for (int eI = 0; eI < 4; eI++) {
                        const float4 v = *(const float4*)(cbb + (kb + eI) * 128 +
                            ((jg * 16) ^ (((kb + eI) & 7) << 4)));
                        cj0[eI] = pk2(v.x, v.y);
                        cj1[eI] = pk2(v.z, v.w);
                    }
                    #pragma unroll
                    for (int n2 = 0; n2 < 8; n2++) {
                        const float4 qv =
                            *(const float4*)(gq + (size_t)n2 * 8192 + kb);
                        u64 dx = dup2(qv.x), dy = dup2(qv.y);
                        u64 dz = dup2(qv.z), dw = dup2(qv.w);
                        fma2(acc[n2][0], dx, cj0[0]); fma2(acc[n2][1], dx, cj1[0]);
                        fma2(acc[n2][0], dy, cj0[1]); fma2(acc[n2][1], dy, cj1[1]);
                        fma2(acc[n2][0], dz, cj0[2]); fma2(acc[n2][1], dz, cj1[2]);
                        fma2(acc[n2][0], dw, cj0[3]); fma2(acc[n2][1], dw, cj1[3]);
                    }
                }
                #pragma unroll
                for (int n2 = 0; n2 < 8; n2++) {
                    acc[n2][0] = add2(acc[n2][0], shfl_xor64(acc[n2][0], 8));
                    acc[n2][1] = add2(acc[n2][1], shfl_xor64(acc[n2][1], 8));
                    acc[n2][0] = add2(acc[n2][0], shfl_xor64(acc[n2][0], 16));
                    acc[n2][1] = add2(acc[n2][1], shfl_xor64(acc[n2][1], 16));
                }
                u64 r0a = acc[0][0], r1a = acc[0][1];
                u64 r0b = acc[1][0], r1b = acc[1][1];
                if (ks == 1) { r0a = acc[2][0]; r1a = acc[2][1];
                               r0b = acc[3][0]; r1b = acc[3][1]; }
                if (ks == 2) { r0a = acc[4][0]; r1a = acc[4][1];
                               r0b = acc[5][0]; r1b = acc[5][1]; }
                if (ks == 3) { r0a = acc[6][0]; r1a = acc[6][1];
                               r0b = acc[7][0]; r1b = acc[7][1]; }
                float a0, a1, a2, a3;
                float* rd = red + (i & 1) * 2048;
                unpk2(r0a, a0, a1); unpk2(r1a, a2, a3);
                *(float4*)(rd + s3 * 256 + (ks * 2) * 32 + jg * 4) =
                    make_float4(a0, a1, a2, a3);
                unpk2(r0b, a0, a1); unpk2(r1b, a2, a3);
                *(float4*)(rd + s3 * 256 + (ks * 2 + 1) * 32 + jg * 4) =
                    make_float4(a0, a1, a2, a3);

                // vectorized qbar: thread owns k = 4*t2 .. 4*t2+3
                #pragma unroll
                for (int n2 = 0; n2 < 8; n2++) {
                    ulonglong2 qq =
                        *(const ulonglong2*)(gq + (size_t)n2 * 8192 + 4 * t2);
                    qbs0 = add2(qbs0, qq.x);
                    qbs1 = add2(qbs1, qq.y);
                }
            }

            // ---- quantized + indices for tile (i-1) ----
            if (i >= s + 1) {
                const int ti = i - 1;
                {
                    int ni0 = t2 & 7, jq = t2 >> 3;
                    int n = ti * 8 + ni0, b = n >> 10;
                    int kq = idxs[(ti % 3) * 8 + ni0];
                    out[(size_t)(b * 256 + c * 32 + jq) * 1024 + (n & 1023)] =
                        cb_el(cbb, kq, jq);
                }
                if (t2 < 8) {
                    int n = ti * 8 + t2, b = n >> 10;
                    out[O_IDX + (size_t)b * 8192 + c * 1024 + (n & 1023)] =
                        (float)idxs[(ti % 3) * 8 + t2];
                }
            }
        }
        __syncthreads();
    }

    // ---- flush accumulators ----
    #pragma unroll
    for (int off = 16; off; off >>= 1) {
        ct_comm += __shfl_xor_sync(0xffffffffu, ct_comm, off);
        zsq_acc += __shfl_xor_sync(0xffffffffu, zsq_acc, off);
    }
    if (lane == 0) {
        atomicAdd(&g_comm, ct_comm);
        atomicAdd(&g_qd, zsq_acc + ((w < 8) ? acc_qd : 0.0f));
        if (w < 8) atomicAdd(&g_ne, acc_ne);
    }
    if (w >= 8) {
        float a, b2;
        unpk2(qbs0, a, b2);
        atomicAdd(&g_qbar[c * 1024 + 4 * t2 + 0], a);
        atomicAdd(&g_qbar[c * 1024 + 4 * t2 + 1], b2);
        unpk2(qbs1, a, b2);
        atomicAdd(&g_qbar[c * 1024 + 4 * t2 + 2], a);
        atomicAdd(&g_qbar[c * 1024 + 4 * t2 + 3], b2);
    }

    // ---- last-block finalize (ticket) ----
    __threadfence();
    int* flag = (int*)(sm + OFF_FLG);
    if (t == 0) {
        unsigned int v = atomicAdd(&g_count, 1u);
        flag[0] = (v == (unsigned)(NBLOCKS - 1));
    }
    __syncthreads();
    if (flag[0]) {
        float local = 0.0f;
        #pragma unroll
        for (int it = 0; it < 16; it++) {
            int idx = t + it * THREADS;
            float qb = g_qbar[idx] * (1.0f / 4096.0f);
            local += qb * __logf(fmaf(qb, 1024.0f, 1e-8f));
            g_qbar[idx] = 0.0f;                 // reset for next graph replay
        }
        #pragma unroll
        for (int off = 16; off; off >>= 1)
            local += __shfl_xor_sync(0xffffffffu, local, off);
        if (lane == 0) scr[w] = local;
        __syncthreads();
        if (t == 0) {
            float sr = 0.0f;
            #pragma unroll
            for (int ii = 0; ii < 16; ii++) sr += scr[ii];
            float balance = sr * 0.125f;
            float comm = g_comm * (1.0f / 1048576.0f);
            float mne  = g_ne   * (1.0f / 32768.0f);
            float mqd  = g_qd   * (1.0f / 32768.0f);
            out[O_SC + 0] = comm;
            out[O_SC + 1] = fmaf(mqd, 0.5f, mne) + 6.93147180559945f;
            out[O_SC + 2] = -mne;
            out[O_SC + 3] = balance;
            out[O_SC + 4] = 1.0f;
            g_comm = 0.0f; g_ne = 0.0f; g_qd = 0.0f;
            g_count = 0u;
        }
    }
}

extern "C" void kernel_launch(void* const* d_in, const int* in_sizes, int n_in,
                              void* d_out, int out_size)
{
    const float* z   = (const float*)d_in[0];   // (4,256,32,32) f32
    const float* cbg = (const float*)d_in[1];   // (8,1024,32)  f32
    float* out = (float*)d_out;

    cudaFuncSetAttribute(lgq_main, cudaFuncAttributeMaxDynamicSharedMemorySize,
                         SMEM_BYTES);
    lgq_main<<<NBLOCKS, THREADS, SMEM_BYTES>>>(z, cbg, out);
}

// round 16
// speedup vs baseline: 1.1561x; 1.0473x over previous
#include <cuda_runtime.h>

typedef unsigned long long u64;

// ---------------- problem constants ----------------
#define CC 8
#define KK 1024
#define THREADS 512
#define NBLOCKS 144            // 18 blocks per codebook, zero cb switches
#define BPC 18

// ---------------- smem layout (float offsets) ----------------
#define OFF_CB   0             // 32768: 1024 rows x 128B, SW128-swizzled
#define OFF_DS   32768         // 16384: 2 x [8 n][1024 k] dists (canonical)
#define OFF_ZFT  49152         // 512:   2 x [32 j][8 n]
#define OFF_ZFTT 49664         // 1320:  5 x [8 n][stride 33 j]
#define OFF_RED  50984         // 4096:  2 x [8 slab][8 n][32 j]
#define OFF_IDX  55080         // 24 ints (3 x 8)
#define OFF_FLG  55104         // 1
#define OFF_SCR  55108         // 16
#define SMEM_FLOATS 55124
#define SMEM_BYTES (SMEM_FLOATS * 4)   // 220496 B

// ---------------- output packing (float32, tuple order) ----------------
#define O_IDX   1048576u
#define O_Q     1081344u
#define O_SC    34635776u

// ---------------- global scratch ----------------
__device__ float g_qbar[CC * KK];
__device__ float g_comm;
__device__ float g_ne;
__device__ float g_qd;
__device__ unsigned int g_count;

// ---------------- f32x2 helpers ----------------
__device__ __forceinline__ void fma2(u64 &d, u64 a, u64 b) {
    asm("fma.rn.f32x2 %0, %1, %2, %0;" : "+l"(d) : "l"(a), "l"(b));
}
__device__ __forceinline__ u64 add2(u64 a, u64 b) {
    u64 r; asm("add.rn.f32x2 %0, %1, %2;" : "=l"(r) : "l"(a), "l"(b)); return r;
}
__device__ __forceinline__ u64 dup2(float x) {
    u64 r; asm("mov.b64 %0, {%1, %1};" : "=l"(r) : "f"(x)); return r;
}
__device__ __forceinline__ u64 pk2(float lo, float hi) {
    u64 r; asm("mov.b64 %0, {%1, %2};" : "=l"(r) : "f"(lo), "f"(hi)); return r;
}
__device__ __forceinline__ void unpk2(u64 v, float &lo, float &hi) {
    asm("mov.b64 {%0, %1}, %2;" : "=f"(lo), "=f"(hi) : "l"(v));
}
__device__ __forceinline__ u64 shfl_xor64(u64 v, int m) {
    return __shfl_xor_sync(0xffffffffu, v, m);
}

// ---------------- swizzled codebook addressing (128B rows, SW128) ----------
__device__ __forceinline__ const float4* cb_vec(const char* cbb, int k, int j4) {
    return (const float4*)(cbb + k * 128 + ((j4 * 16) ^ ((k & 7) << 4)));
}
__device__ __forceinline__ float cb_el(const char* cbb, int k, int j) {
    return *(const float*)(cbb + k * 128 + ((j * 4) ^ ((k & 7) << 4)));
}

__global__ void __launch_bounds__(THREADS, 1)
lgq_main(const float* __restrict__ z, const float* __restrict__ cbg,
         float* __restrict__ out)
{
    extern __shared__ float sm[];
    char*  cbb  = (char*)sm;
    float* ds   = sm + OFF_DS;
    float* zft  = sm + OFF_ZFT;
    float* zftT = sm + OFF_ZFTT;
    float* red  = sm + OFF_RED;
    int*   idxs = (int*)(sm + OFF_IDX);
    float* scr  = sm + OFF_SCR;

    const int t    = threadIdx.x;
    const int w    = t >> 5;
    const int lane = t & 31;
    const int bx   = blockIdx.x;

    const int c  = bx / BPC;
    const int bi = bx % BPC;
    const int s  = bi * 28 + min(bi, 8);
    const int e  = s + 28 + (bi < 8 ? 1 : 0);

    // ---- stage codebook c (swizzled) ----
    {
        const float4* cb4 = (const float4*)(cbg + (size_t)c * (KK * 32));
        #pragma unroll
        for (int it = 0; it < 16; it++) {
            int idx = t + it * THREADS;
            float4 v = cb4[idx];
            int k = idx >> 3, j4 = idx & 7;
            *(float4*)(cbb + k * 128 + ((j4 * 16) ^ ((k & 7) << 4))) = v;
        }
    }
    float zsq_acc = 0.0f;
    // ---- prestage zf(tile s) ----
    if (t < 256) {
        int jj0 = t >> 3, ni0 = t & 7;
        int n = s * 8 + ni0, b = n >> 10;
        float v = z[(size_t)(b * 256 + c * 32 + jj0) * 1024 + (n & 1023)];
        zft[(s & 1) * 256 + jj0 * 8 + ni0]   = v;
        zftT[(s % 5) * 264 + ni0 * 33 + jj0] = v;
        zsq_acc = v * v;
    }
    __syncthreads();

    // ---- codeword norms for k0 + 256m (p1 warps) ----
    const int k0 = t & 255;
    float cq[4];
    #pragma unroll
    for (int m = 0; m < 4; m++) {
        int k = k0 + 256 * m;
        float sq = 0.0f;
        #pragma unroll
        for (int j4 = 0; j4 < 8; j4++) {
            float4 v = *cb_vec(cbb, k, j4);
            sq += v.x * v.x + v.y * v.y + v.z * v.z + v.w * v.w;
        }
        cq[m] = sq;
    }

    float acc_ne = 0.0f, acc_qd = 0.0f, ct_comm = 0.0f;
    float qbr0 = 0.0f, qbr1 = 0.0f, qbr2 = 0.0f, qbr3 = 0.0f;
    const int t2 = t - 256;    // consumer-group thread id (w >= 8)

    // =====================================================================
    // ONE barrier per iteration. Iter i:
    //   P (w<8):  LDG zf(i+3) | p1(i+2)->ds[i&1] | p2(i+1) (q -> GLOBAL) |
    //             outputs+commitment(i-1) | STS zf(i+3)
    //   C (w>=8): p3(i) from GLOBAL q -> red[i%2] | qbar(i) from GLOBAL q
    // =====================================================================
    for (int i = s - 2; i <= e; i++) {
        if (w < 8) {
            // ---- LDG zf(i+3) ----
            float zn = 0.0f;
            const bool ldg_ok = (i + 3 < e);
            const int jj0 = t >> 3, ni0 = t & 7;
            if (ldg_ok) {
                int n = (i + 3) * 8 + ni0, b = n >> 10;
                zn = z[(size_t)(b * 256 + c * 32 + jj0) * 1024 + (n & 1023)];
            }

            // ---- p1(i+2): dists -> ds[i&1] ----
            if (i + 2 < e) {
                u64 acc[4][4];
                #pragma unroll
                for (int np = 0; np < 4; np++)
                    #pragma unroll
                    for (int m = 0; m < 4; m++) acc[np][m] = 0ull;

                const int sx = (k0 & 7) << 4;
                const float* zb = zft + ((i + 2) & 1) * 256;
                float* dsb = ds + (i & 1) * 8192;   // (i+2)&1 == i&1

                #pragma unroll
                for (int j4 = 0; j4 < 8; j4++) {
                    const int off = (j4 * 16) ^ sx;
                    float4 cv0 = *(const float4*)(cbb + k0 * 128 + off);
                    float4 cv1 = *(const float4*)(cbb + (k0 + 256) * 128 + off);
                    float4 cv2 = *(const float4*)(cbb + (k0 + 512) * 128 + off);
                    float4 cv3 = *(const float4*)(cbb + (k0 + 768) * 128 + off);
                    #pragma unroll
                    for (int eI = 0; eI < 4; eI++) {
                        const ulonglong2* zp =
                            (const ulonglong2*)(zb + (j4 * 4 + eI) * 8);
                        ulonglong2 zA = zp[0], zB = zp[1];
                        float e0 = (eI == 0) ? cv0.x : (eI == 1) ? cv0.y
                                 : (eI == 2) ? cv0.z : cv0.w;
                        float e1 = (eI == 0) ? cv1.x : (eI == 1) ? cv1.y
                                 : (eI == 2) ? cv1.z : cv1.w;
                        float e2 = (eI == 0) ? cv2.x : (eI == 1) ? cv2.y
                                 : (eI == 2) ? cv2.z : cv2.w;
                        float e3 = (eI == 0) ? cv3.x : (eI == 1) ? cv3.y
                                 : (eI == 2) ? cv3.z : cv3.w;
                        u64 d0 = dup2(e0), d1 = dup2(e1);
                        u64 d2 = dup2(e2), d3 = dup2(e3);
                        fma2(acc[0][0], zA.x, d0); fma2(acc[0][1], zA.x, d1);
                        fma2(acc[0][2], zA.x, d2); fma2(acc[0][3], zA.x, d3);
                        fma2(acc[1][0], zA.y, d0); fma2(acc[1][1], zA.y, d1);
                        fma2(acc[1][2], zA.y, d2); fma2(acc[1][3], zA.y, d3);
                        fma2(acc[2][0], zB.x, d0); fma2(acc[2][1], zB.x, d1);
                        fma2(acc[2][2], zB.x, d2); fma2(acc[2][3], zB.x, d3);
                        fma2(acc[3][0], zB.y, d0); fma2(acc[3][1], zB.y, d1);
                        fma2(acc[3][2], zB.y, d2); fma2(acc[3][3], zB.y, d3);
                    }
                }
                #pragma unroll
                for (int np = 0; np < 4; np++)
                    #pragma unroll
                    for (int m = 0; m < 4; m++) {
                        float a, b2; unpk2(acc[np][m], a, b2);
                        int k = k0 + 256 * m;
                        dsb[(2 * np) * 1024 + k]     = fmaf(-2.0f, a,  cq[m]);
                        dsb[(2 * np + 1) * 1024 + k] = fmaf(-2.0f, b2, cq[m]);
                    }
            }

            // ---- p2(i+1): softmax/argmin row w; q -> GLOBAL only ----
            if (i + 1 >= s && i + 1 < e) {
                const float* row = ds + ((i + 1) & 1) * 8192 + w * 1024;
                const float4* row4 = (const float4*)row;
                float dv[32];
                #pragma unroll
                for (int m4 = 0; m4 < 8; m4++) {
                    float4 v = row4[lane + 32 * m4];
                    dv[m4 * 4 + 0] = v.x; dv[m4 * 4 + 1] = v.y;
                    dv[m4 * 4 + 2] = v.z; dv[m4 * 4 + 3] = v.w;
                }
                // --- min value: fminf tree (ILP), then warp reduce ---
                float mm[16];
                #pragma unroll
                for (int ii = 0; ii < 16; ii++)
                    mm[ii] = fminf(dv[ii], dv[ii + 16]);
                #pragma unroll
                for (int st = 8; st; st >>= 1)
                    #pragma unroll
                    for (int ii = 0; ii < st; ii++)
                        mm[ii] = fminf(mm[ii], mm[ii + st]);
                float rmin = mm[0];
                #pragma unroll
                for (int off = 16; off; off >>= 1)
                    rmin = fminf(rmin, __shfl_xor_sync(0xffffffffu, rmin, off));
                // --- index: equality scan, 4 independent chains ---
                int km0 = 1 << 30, km1 = 1 << 30, km2 = 1 << 30, km3 = 1 << 30;
                #pragma unroll
                for (int m4 = 0; m4 < 8; m4++) {
                    int kb = 4 * lane + 128 * m4;
                    if (dv[m4 * 4 + 0] == rmin) km0 = min(km0, kb + 0);
                    if (dv[m4 * 4 + 1] == rmin) km1 = min(km1, kb + 1);
                    if (dv[m4 * 4 + 2] == rmin) km2 = min(km2, kb + 2);
                    if (dv[m4 * 4 + 3] == rmin) km3 = min(km3, kb + 3);
                }
                int kmin = min(min(km0, km1), min(km2, km3));
                #pragma unroll
                for (int off = 16; off; off >>= 1)
                    kmin = min(kmin, __shfl_xor_sync(0xffffffffu, kmin, off));
                // --- exp + Z/sed with 4 accumulators ---
                float Z0 = 0.0f, Z1 = 0.0f, Z2 = 0.0f, Z3 = 0.0f;
                float s0 = 0.0f, s1 = 0.0f, s2 = 0.0f, s3 = 0.0f;
                #pragma unroll
                for (int m4 = 0; m4 < 8; m4++) {
                    float t0 = dv[m4 * 4 + 0], t1 = dv[m4 * 4 + 1];
                    float t2v = dv[m4 * 4 + 2], t3 = dv[m4 * 4 + 3];
                    float e0 = __expf((rmin - t0) * 0.5f);
                    float e1 = __expf((rmin - t1) * 0.5f);
                    float e2 = __expf((rmin - t2v) * 0.5f);
                    float e3 = __expf((rmin - t3) * 0.5f);
                    Z0 += e0; Z1 += e1; Z2 += e2; Z3 += e3;
                    s0 = fmaf(e0, t0, s0); s1 = fmaf(e1, t1, s1);
                    s2 = fmaf(e2, t2v, s2); s3 = fmaf(e3, t3, s3);
                    dv[m4 * 4 + 0] = e0; dv[m4 * 4 + 1] = e1;
                    dv[m4 * 4 + 2] = e2; dv[m4 * 4 + 3] = e3;
                }
                float Z = (Z0 + Z1) + (Z2 + Z3);
                float sed = (s0 + s1) + (s2 + s3);
                #pragma unroll
                for (int off = 16; off; off >>= 1) {
                    Z   += __shfl_xor_sync(0xffffffffu, Z, off);
                    sed += __shfl_xor_sync(0xffffffffu, sed, off);
                }
                float rZ = __fdividef(1.0f, Z);
                float qd = sed * rZ;

                int n = (i + 1) * 8 + w;
                float4* gq4 = (float4*)(out + O_Q + ((size_t)n * 8 + c) * 1024);
                #pragma unroll
                for (int m4 = 0; m4 < 8; m4++) {
                    float4 qv;
                    qv.x = dv[m4 * 4 + 0] * rZ; qv.y = dv[m4 * 4 + 1] * rZ;
                    qv.z = dv[m4 * 4 + 2] * rZ; qv.w = dv[m4 * 4 + 3] * rZ;
                    gq4[lane + 32 * m4] = qv;
                }
                if (lane == 0) {
                    acc_ne += 0.5f * (rmin - qd) - __logf(Z);
                    acc_qd += qd;
                    idxs[((i + 1) % 3) * 8 + w] = kmin;
                }
            }

            // ---- outputs + commitment for tile (i-1) ----
            if (i >= s + 1) {
                const int ti = i - 1;
                {
                    int ni0 = t & 7, jq = t >> 3;
                    int n = ti * 8 + ni0, b = n >> 10;
                    int kq = idxs[(ti % 3) * 8 + ni0];
                    out[(size_t)(b * 256 + c * 32 + jq) * 1024 + (n & 1023)] =
                        cb_el(cbb, kq, jq);
                }
                if (t < 8) {
                    int n = ti * 8 + t, b = n >> 10;
                    out[O_IDX + (size_t)b * 8192 + c * 1024 + (n & 1023)] =
                        (float)idxs[(ti % 3) * 8 + t];
                }
                {
                    int cn = t >> 5, cj = t & 31;
                    const float* rd = red + (ti & 1) * 2048;
                    float sr = 0.0f;
                    #pragma unroll
                    for (int ss = 0; ss < 8; ss++)
                        sr += rd[ss * 256 + cn * 32 + cj];
                    float diff = zftT[(ti % 5) * 264 + cn * 33 + cj] - sr;
                    ct_comm = fmaf(diff, diff, ct_comm);
                }
            }

            // ---- STS zf(i+3) ----
            if (ldg_ok) {
                zft[((i + 3) & 1) * 256 + jj0 * 8 + ni0]   = zn;
                zftT[((i + 3) % 5) * 264 + ni0 * 33 + jj0] = zn;
                zsq_acc += zn * zn;
            }
        } else {
            // ================= C: p3(i) + qbar(i) from GLOBAL q ===========
            if (i >= s && i < e) {
                const int s3 = w - 8;
                const int ks = lane >> 3;
                const int jg = lane & 7;
                const float* gq = out + O_Q + (size_t)c * 1024
                                + (size_t)i * 8 * 8192;
                u64 acc[8][2];
                #pragma unroll
                for (int n2 = 0; n2 < 8; n2++) { acc[n2][0] = 0ull; acc[n2][1] = 0ull; }

                #pragma unroll
                for (int i4 = 0; i4 < 8; i4++) {
                    const int kb = s3 * 128 + ks * 32 + i4 * 4;
                    u64 cj0[4], cj1[4];
                    #pragma unroll
                    for (int eI = 0; eI < 4; eI++) {
                        const float4 v = *(const float4*)(cbb + (kb + eI) * 128 +
                            ((jg * 16) ^ (((kb + eI) & 7) << 4)));
                        cj0[eI] = pk2(v.x, v.y);
                        cj1[eI] = pk2(v.z, v.w);
                    }
                    #pragma unroll
                    for (int n2 = 0; n2 < 8; n2++) {
                        const float4 qv =
                            *(const float4*)(gq + (size_t)n2 * 8192 + kb);
                        u64 dx = dup2(qv.x), dy = dup2(qv.y);
                        u64 dz = dup2(qv.z), dw = dup2(qv.w);
                        fma2(acc[n2][0], dx, cj0[0]); fma2(acc[n2][1], dx, cj1[0]);
                        fma2(acc[n2][0], dy, cj0[1]); fma2(acc[n2][1], dy, cj1[1]);
                        fma2(acc[n2][0], dz, cj0[2]); fma2(acc[n2][1], dz, cj1[2]);
                        fma2(acc[n2][0], dw, cj0[3]); fma2(acc[n2][1], dw, cj1[3]);
                    }
                }
                #pragma unroll
                for (int n2 = 0; n2 < 8; n2++) {
                    acc[n2][0] = add2(acc[n2][0], shfl_xor64(acc[n2][0], 8));
                    acc[n2][1] = add2(acc[n2][1], shfl_xor64(acc[n2][1], 8));
                    acc[n2][0] = add2(acc[n2][0], shfl_xor64(acc[n2][0], 16));
                    acc[n2][1] = add2(acc[n2][1], shfl_xor64(acc[n2][1], 16));
                }
                u64 r0a = acc[0][0], r1a = acc[0][1];
                u64 r0b = acc[1][0], r1b = acc[1][1];
                if (ks == 1) { r0a = acc[2][0]; r1a = acc[2][1];
                               r0b = acc[3][0]; r1b = acc[3][1]; }
                if (ks == 2) { r0a = acc[4][0]; r1a = acc[4][1];
                               r0b = acc[5][0]; r1b = acc[5][1]; }
                if (ks == 3) { r0a = acc[6][0]; r1a = acc[6][1];
                               r0b = acc[7][0]; r1b = acc[7][1]; }
                float a0, a1, a2, a3;
                float* rd = red + (i & 1) * 2048;
                unpk2(r0a, a0, a1); unpk2(r1a, a2, a3);
                *(float4*)(rd + s3 * 256 + (ks * 2) * 32 + jg * 4) =
                    make_float4(a0, a1, a2, a3);
                unpk2(r0b, a0, a1); unpk2(r1b, a2, a3);
                *(float4*)(rd + s3 * 256 + (ks * 2 + 1) * 32 + jg * 4) =
                    make_float4(a0, a1, a2, a3);

                // qbar from global q (coalesced across t2)
                float s0 = 0.0f, s1 = 0.0f, s2 = 0.0f, s3p = 0.0f;
                #pragma unroll
                for (int n2 = 0; n2 < 8; n2++) {
                    const float* qr = gq + (size_t)n2 * 8192;
                    s0  += qr[t2];
                    s1  += qr[t2 + 256];
                    s2  += qr[t2 + 512];
                    s3p += qr[t2 + 768];
                }
                qbr0 += s0; qbr1 += s1; qbr2 += s2; qbr3 += s3p;
            }
        }
        __syncthreads();
    }

    // ---- flush accumulators ----
    #pragma unroll
    for (int off = 16; off; off >>= 1) {
        ct_comm += __shfl_xor_sync(0xffffffffu, ct_comm, off);
        zsq_acc += __shfl_xor_sync(0xffffffffu, zsq_acc, off);
    }
    if (lane == 0) {
        atomicAdd(&g_comm, ct_comm);
        atomicAdd(&g_qd, zsq_acc + ((w < 8) ? acc_qd : 0.0f));
        if (w < 8) atomicAdd(&g_ne, acc_ne);
    }
    if (w >= 8) {
        atomicAdd(&g_qbar[c * 1024 + t2],       qbr0);
        atomicAdd(&g_qbar[c * 1024 + t2 + 256], qbr1);
        atomicAdd(&g_qbar[c * 1024 + t2 + 512], qbr2);
        atomicAdd(&g_qbar[c * 1024 + t2 + 768], qbr3);
    }

    // ---- last-block finalize (ticket) ----
    __threadfence();
    int* flag = (int*)(sm + OFF_FLG);
    if (t == 0) {
        unsigned int v = atomicAdd(&g_count, 1u);
        flag[0] = (v == (unsigned)(NBLOCKS - 1));
    }
    __syncthreads();
    if (flag[0]) {
        float local = 0.0f;
        #pragma unroll
        for (int it = 0; it < 16; it++) {
            int idx = t + it * THREADS;
            float qb = g_qbar[idx] * (1.0f / 4096.0f);
            local += qb * __logf(fmaf(qb, 1024.0f, 1e-8f));
            g_qbar[idx] = 0.0f;                 // reset for next graph replay
        }
        #pragma unroll
        for (int off = 16; off; off >>= 1)
            local += __shfl_xor_sync(0xffffffffu, local, off);
        if (lane == 0) scr[w] = local;
        __syncthreads();
        if (t == 0) {
            float sr = 0.0f;
            #pragma unroll
            for (int ii = 0; ii < 16; ii++) sr += scr[ii];
            float balance = sr * 0.125f;
            float comm = g_comm * (1.0f / 1048576.0f);
            float mne  = g_ne   * (1.0f / 32768.0f);
            float mqd  = g_qd   * (1.0f / 32768.0f);
            out[O_SC + 0] = comm;
            out[O_SC + 1] = fmaf(mqd, 0.5f, mne) + 6.93147180559945f;
            out[O_SC + 2] = -mne;
            out[O_SC + 3] = balance;
            out[O_SC + 4] = 1.0f;
            g_comm = 0.0f; g_ne = 0.0f; g_qd = 0.0f;
            g_count = 0u;
        }
    }
}

extern "C" void kernel_launch(void* const* d_in, const int* in_sizes, int n_in,
                              void* d_out, int out_size)
{
    const float* z   = (const float*)d_in[0];   // (4,256,32,32) f32
    const float* cbg = (const float*)d_in[1];   // (8,1024,32)  f32
    float* out = (float*)d_out;

    cudaFuncSetAttribute(lgq_main, cudaFuncAttributeMaxDynamicSharedMemorySize,
                         SMEM_BYTES);
    lgq_main<<<NBLOCKS, THREADS, SMEM_BYTES>>>(z, cbg, out);
}

// round 17
// speedup vs baseline: 1.1617x; 1.0048x over previous
#include <cuda_runtime.h>

typedef unsigned long long u64;

// ---------------- problem constants ----------------
#define CC 8
#define KK 1024
#define THREADS 512
#define NBLOCKS 144            // 18 blocks per codebook, zero cb switches
#define BPC 18

// ---------------- smem layout (float offsets) ----------------
#define OFF_CB   0             // 32768: 1024 rows x 128B, SW128-swizzled
#define OFF_DS   32768         // 16384: 2 x [8 n][1024 k] dists (canonical)
#define OFF_ZFT  49152         // 512:   2 x [32 j][8 n]
#define OFF_ZFTT 49664         // 1320:  5 x [8 n][stride 33 j]
#define OFF_RED  50984         // 4096:  2 x [8 slab][8 n][32 j]
#define OFF_IDX  55080         // 24 ints (3 x 8)
#define OFF_FLG  55104         // 1
#define OFF_SCR  55108         // 16
#define SMEM_FLOATS 55124
#define SMEM_BYTES (SMEM_FLOATS * 4)   // 220496 B

// ---------------- output packing (float32, tuple order) ----------------
#define O_IDX   1048576u
#define O_Q     1081344u
#define O_SC    34635776u

// ---------------- global scratch ----------------
__device__ float g_qbar[CC * KK];
__device__ float g_comm;
__device__ float g_ne;
__device__ float g_qd;
__device__ unsigned int g_count;

// ---------------- f32x2 helpers ----------------
__device__ __forceinline__ void fma2(u64 &d, u64 a, u64 b) {
    asm("fma.rn.f32x2 %0, %1, %2, %0;" : "+l"(d) : "l"(a), "l"(b));
}
__device__ __forceinline__ u64 add2(u64 a, u64 b) {
    u64 r; asm("add.rn.f32x2 %0, %1, %2;" : "=l"(r) : "l"(a), "l"(b)); return r;
}
__device__ __forceinline__ u64 dup2(float x) {
    u64 r; asm("mov.b64 %0, {%1, %1};" : "=l"(r) : "f"(x)); return r;
}
__device__ __forceinline__ u64 pk2(float lo, float hi) {
    u64 r; asm("mov.b64 %0, {%1, %2};" : "=l"(r) : "f"(lo), "f"(hi)); return r;
}
__device__ __forceinline__ void unpk2(u64 v, float &lo, float &hi) {
    asm("mov.b64 {%0, %1}, %2;" : "=f"(lo), "=f"(hi) : "l"(v));
}
__device__ __forceinline__ u64 shfl_xor64(u64 v, int m) {
    return __shfl_xor_sync(0xffffffffu, v, m);
}

// ---------------- swizzled codebook addressing (128B rows, SW128) ----------
__device__ __forceinline__ const float4* cb_vec(const char* cbb, int k, int j4) {
    return (const float4*)(cbb + k * 128 + ((j4 * 16) ^ ((k & 7) << 4)));
}
__device__ __forceinline__ float cb_el(const char* cbb, int k, int j) {
    return *(const float*)(cbb + k * 128 + ((j * 4) ^ ((k & 7) << 4)));
}

__global__ void __launch_bounds__(THREADS, 1)
lgq_main(const float* __restrict__ z, const float* __restrict__ cbg,
         float* __restrict__ out)
{
    extern __shared__ float sm[];
    char*  cbb  = (char*)sm;
    float* ds   = sm + OFF_DS;
    float* zft  = sm + OFF_ZFT;
    float* zftT = sm + OFF_ZFTT;
    float* red  = sm + OFF_RED;
    int*   idxs = (int*)(sm + OFF_IDX);
    float* scr  = sm + OFF_SCR;

    const int t    = threadIdx.x;
    const int w    = t >> 5;
    const int lane = t & 31;
    const int bx   = blockIdx.x;

    const int c  = bx / BPC;
    const int bi = bx % BPC;
    const int s  = bi * 28 + min(bi, 8);
    const int e  = s + 28 + (bi < 8 ? 1 : 0);

    // ---- stage codebook c (swizzled) ----
    {
        const float4* cb4 = (const float4*)(cbg + (size_t)c * (KK * 32));
        #pragma unroll
        for (int it = 0; it < 16; it++) {
            int idx = t + it * THREADS;
            float4 v = cb4[idx];
            int k = idx >> 3, j4 = idx & 7;
            *(float4*)(cbb + k * 128 + ((j4 * 16) ^ ((k & 7) << 4))) = v;
        }
    }
    float zsq_acc = 0.0f;
    // ---- prestage zf(tile s) ----
    if (t < 256) {
        int jj0 = t >> 3, ni0 = t & 7;
        int n = s * 8 + ni0, b = n >> 10;
        float v = z[(size_t)(b * 256 + c * 32 + jj0) * 1024 + (n & 1023)];
        zft[(s & 1) * 256 + jj0 * 8 + ni0]   = v;
        zftT[(s % 5) * 264 + ni0 * 33 + jj0] = v;
        zsq_acc = v * v;
    }
    __syncthreads();

    // ---- codeword norms for k0 + 256m (p1 warps) ----
    const int k0 = t & 255;
    float cq[4];
    #pragma unroll
    for (int m = 0; m < 4; m++) {
        int k = k0 + 256 * m;
        float sq = 0.0f;
        #pragma unroll
        for (int j4 = 0; j4 < 8; j4++) {
            float4 v = *cb_vec(cbb, k, j4);
            sq += v.x * v.x + v.y * v.y + v.z * v.z + v.w * v.w;
        }
        cq[m] = sq;
    }

    float acc_ne = 0.0f, acc_qd = 0.0f, ct_comm = 0.0f;
    u64 qbs0 = 0ull, qbs1 = 0ull;      // qbar pairs for k = 4*t2 .. 4*t2+3
    const int t2 = t - 256;            // consumer-group thread id (w >= 8)

    // =====================================================================
    // ONE barrier per iteration. Iter i:
    //   P (w<8):  LDG zf(i+3) | p1(i+2)->ds[i&1] | p2(i+1) (q -> GLOBAL) |
    //             outputs+commitment(i-1) | STS zf(i+3)
    //   C (w>=8): p3(i) from GLOBAL q -> red[i%2] | qbar(i) vectorized
    // =====================================================================
    for (int i = s - 2; i <= e; i++) {
        if (w < 8) {
            // ---- LDG zf(i+3) ----
            float zn = 0.0f;
            const bool ldg_ok = (i + 3 < e);
            const int jj0 = t >> 3, ni0 = t & 7;
            if (ldg_ok) {
                int n = (i + 3) * 8 + ni0, b = n >> 10;
                zn = z[(size_t)(b * 256 + c * 32 + jj0) * 1024 + (n & 1023)];
            }

            // ---- p1(i+2): dists -> ds[i&1] ----
            if (i + 2 < e) {
                u64 acc[4][4];
                #pragma unroll
                for (int np = 0; np < 4; np++)
                    #pragma unroll
                    for (int m = 0; m < 4; m++) acc[np][m] = 0ull;

                const int sx = (k0 & 7) << 4;
                const float* zb = zft + ((i + 2) & 1) * 256;
                float* dsb = ds + (i & 1) * 8192;   // (i+2)&1 == i&1

                #pragma unroll
                for (int j4 = 0; j4 < 8; j4++) {
                    const int off = (j4 * 16) ^ sx;
                    float4 cv0 = *(const float4*)(cbb + k0 * 128 + off);
                    float4 cv1 = *(const float4*)(cbb + (k0 + 256) * 128 + off);
                    float4 cv2 = *(const float4*)(cbb + (k0 + 512) * 128 + off);
                    float4 cv3 = *(const float4*)(cbb + (k0 + 768) * 128 + off);
                    #pragma unroll
                    for (int eI = 0; eI < 4; eI++) {
                        const ulonglong2* zp =
                            (const ulonglong2*)(zb + (j4 * 4 + eI) * 8);
                        ulonglong2 zA = zp[0], zB = zp[1];
                        float e0 = (eI == 0) ? cv0.x : (eI == 1) ? cv0.y
                                 : (eI == 2) ? cv0.z : cv0.w;
                        float e1 = (eI == 0) ? cv1.x : (eI == 1) ? cv1.y
                                 : (eI == 2) ? cv1.z : cv1.w;
                        float e2 = (eI == 0) ? cv2.x : (eI == 1) ? cv2.y
                                 : (eI == 2) ? cv2.z : cv2.w;
                        float e3 = (eI == 0) ? cv3.x : (eI == 1) ? cv3.y
                                 : (eI == 2) ? cv3.z : cv3.w;
                        u64 d0 = dup2(e0), d1 = dup2(e1);
                        u64 d2 = dup2(e2), d3 = dup2(e3);
                        fma2(acc[0][0], zA.x, d0); fma2(acc[0][1], zA.x, d1);
                        fma2(acc[0][2], zA.x, d2); fma2(acc[0][3], zA.x, d3);
                        fma2(acc[1][0], zA.y, d0); fma2(acc[1][1], zA.y, d1);
                        fma2(acc[1][2], zA.y, d2); fma2(acc[1][3], zA.y, d3);
                        fma2(acc[2][0], zB.x, d0); fma2(acc[2][1], zB.x, d1);
                        fma2(acc[2][2], zB.x, d2); fma2(acc[2][3], zB.x, d3);
                        fma2(acc[3][0], zB.y, d0); fma2(acc[3][1], zB.y, d1);
                        fma2(acc[3][2], zB.y, d2); fma2(acc[3][3], zB.y, d3);
                    }
                }
                #pragma unroll
                for (int np = 0; np < 4; np++)
                    #pragma unroll
                    for (int m = 0; m < 4; m++) {
                        float a, b2; unpk2(acc[np][m], a, b2);
                        int k = k0 + 256 * m;
                        dsb[(2 * np) * 1024 + k]     = fmaf(-2.0f, a,  cq[m]);
                        dsb[(2 * np + 1) * 1024 + k] = fmaf(-2.0f, b2, cq[m]);
                    }
            }

            // ---- p2(i+1): softmax/argmin row w; q -> GLOBAL only ----
            if (i + 1 >= s && i + 1 < e) {
                const float* row = ds + ((i + 1) & 1) * 8192 + w * 1024;
                const float4* row4 = (const float4*)row;
                float dv[32];
                #pragma unroll
                for (int m4 = 0; m4 < 8; m4++) {
                    float4 v = row4[lane + 32 * m4];
                    dv[m4 * 4 + 0] = v.x; dv[m4 * 4 + 1] = v.y;
                    dv[m4 * 4 + 2] = v.z; dv[m4 * 4 + 3] = v.w;
                }
                // --- min value: fminf tree (ILP), then warp reduce ---
                float mm[16];
                #pragma unroll
                for (int ii = 0; ii < 16; ii++)
                    mm[ii] = fminf(dv[ii], dv[ii + 16]);
                #pragma unroll
                for (int st = 8; st; st >>= 1)
                    #pragma unroll
                    for (int ii = 0; ii < st; ii++)
                        mm[ii] = fminf(mm[ii], mm[ii + st]);
                float rmin = mm[0];
                #pragma unroll
                for (int off = 16; off; off >>= 1)
                    rmin = fminf(rmin, __shfl_xor_sync(0xffffffffu, rmin, off));
                // --- index: equality scan, 4 independent chains ---
                int km0 = 1 << 30, km1 = 1 << 30, km2 = 1 << 30, km3 = 1 << 30;
                #pragma unroll
                for (int m4 = 0; m4 < 8; m4++) {
                    int kb = 4 * lane + 128 * m4;
                    if (dv[m4 * 4 + 0] == rmin) km0 = min(km0, kb + 0);
                    if (dv[m4 * 4 + 1] == rmin) km1 = min(km1, kb + 1);
                    if (dv[m4 * 4 + 2] == rmin) km2 = min(km2, kb + 2);
                    if (dv[m4 * 4 + 3] == rmin) km3 = min(km3, kb + 3);
                }
                int kmin = min(min(km0, km1), min(km2, km3));
                #pragma unroll
                for (int off = 16; off; off >>= 1)
                    kmin = min(kmin, __shfl_xor_sync(0xffffffffu, kmin, off));
                // --- exp + Z/sed with 4 accumulators ---
                float Z0 = 0.0f, Z1 = 0.0f, Z2 = 0.0f, Z3 = 0.0f;
                float s0 = 0.0f, s1 = 0.0f, s2 = 0.0f, s3 = 0.0f;
                #pragma unroll
                for (int m4 = 0; m4 < 8; m4++) {
                    float t0 = dv[m4 * 4 + 0], t1 = dv[m4 * 4 + 1];
                    float t2v = dv[m4 * 4 + 2], t3 = dv[m4 * 4 + 3];
                    float e0 = __expf((rmin - t0) * 0.5f);
                    float e1 = __expf((rmin - t1) * 0.5f);
                    float e2 = __expf((rmin - t2v) * 0.5f);
                    float e3 = __expf((rmin - t3) * 0.5f);
                    Z0 += e0; Z1 += e1; Z2 += e2; Z3 += e3;
                    s0 = fmaf(e0, t0, s0); s1 = fmaf(e1, t1, s1);
                    s2 = fmaf(e2, t2v, s2); s3 = fmaf(e3, t3, s3);
                    dv[m4 * 4 + 0] = e0; dv[m4 * 4 + 1] = e1;
                    dv[m4 * 4 + 2] = e2; dv[m4 * 4 + 3] = e3;
                }
                float Z = (Z0 + Z1) + (Z2 + Z3);
                float sed = (s0 + s1) + (s2 + s3);
                #pragma unroll
                for (int off = 16; off; off >>= 1) {
                    Z   += __shfl_xor_sync(0xffffffffu, Z, off);
                    sed += __shfl_xor_sync(0xffffffffu, sed, off);
                }
                float rZ = __fdividef(1.0f, Z);
                float qd = sed * rZ;

                int n = (i + 1) * 8 + w;
                float4* gq4 = (float4*)(out + O_Q + ((size_t)n * 8 + c) * 1024);
                #pragma unroll
                for (int m4 = 0; m4 < 8; m4++) {
                    float4 qv;
                    qv.x = dv[m4 * 4 + 0] * rZ; qv.y = dv[m4 * 4 + 1] * rZ;
                    qv.z = dv[m4 * 4 + 2] * rZ; qv.w = dv[m4 * 4 + 3] * rZ;
                    gq4[lane + 32 * m4] = qv;
                }
                if (lane == 0) {
                    acc_ne += 0.5f * (rmin - qd) - __logf(Z);
                    acc_qd += qd;
                    idxs[((i + 1) % 3) * 8 + w] = kmin;
                }
            }

            // ---- outputs + commitment for tile (i-1) ----
            if (i >= s + 1) {
                const int ti = i - 1;
                {
                    int ni0 = t & 7, jq = t >> 3;
                    int n = ti * 8 + ni0, b = n >> 10;
                    int kq = idxs[(ti % 3) * 8 + ni0];
                    out[(size_t)(b * 256 + c * 32 + jq) * 1024 + (n & 1023)] =
                        cb_el(cbb, kq, jq);
                }
                if (t < 8) {
                    int n = ti * 8 + t, b = n >> 10;
                    out[O_IDX + (size_t)b * 8192 + c * 1024 + (n & 1023)] =
                        (float)idxs[(ti % 3) * 8 + t];
                }
                {
                    int cn = t >> 5, cj = t & 31;
                    const float* rd = red + (ti & 1) * 2048;
                    float sr = 0.0f;
                    #pragma unroll
                    for (int ss = 0; ss < 8; ss++)
                        sr += rd[ss * 256 + cn * 32 + cj];
                    float diff = zftT[(ti % 5) * 264 + cn * 33 + cj] - sr;
                    ct_comm = fmaf(diff, diff, ct_comm);
                }
            }

            // ---- STS zf(i+3) ----
            if (ldg_ok) {
                zft[((i + 3) & 1) * 256 + jj0 * 8 + ni0]   = zn;
                zftT[((i + 3) % 5) * 264 + ni0 * 33 + jj0] = zn;
                zsq_acc += zn * zn;
            }
        } else {
            // ===== C: p3(i) + vectorized qbar(i) from GLOBAL q ============
            if (i >= s && i < e) {
                const int s3 = w - 8;
                const int ks = lane >> 3;
                const int jg = lane & 7;
                const float* gq = out + O_Q + (size_t)c * 1024
                                + (size_t)i * 8 * 8192;
                u64 acc[8][2];
                #pragma unroll
                for (int n2 = 0; n2 < 8; n2++) { acc[n2][0] = 0ull; acc[n2][1] = 0ull; }

                #pragma unroll
                for (int i4 = 0; i4 < 8; i4++) {
                    const int kb = s3 * 128 + ks * 32 + i4 * 4;
                    u64 cj0[4], cj1[4];
                    #pragma unroll
                    for (int eI = 0; eI < 4; eI++) {
                        const float4 v = *(const float4*)(cbb + (kb + eI) * 128 +
                            ((jg * 16) ^ (((kb + eI) & 7) << 4)));
                        cj0[eI] = pk2(v.x, v.y);
                        cj1[eI] = pk2(v.z, v.w);
                    }
                    #pragma unroll
                    for (int n2 = 0; n2 < 8; n2++) {
                        const float4 qv =
                            *(const float4*)(gq + (size_t)n2 * 8192 + kb);
                        u64 dx = dup2(qv.x), dy = dup2(qv.y);
                        u64 dz = dup2(qv.z), dw = dup2(qv.w);
                        fma2(acc[n2][0], dx, cj0[0]); fma2(acc[n2][1], dx, cj1[0]);
                        fma2(acc[n2][0], dy, cj0[1]); fma2(acc[n2][1], dy, cj1[1]);
                        fma2(acc[n2][0], dz, cj0[2]); fma2(acc[n2][1], dz, cj1[2]);
                        fma2(acc[n2][0], dw, cj0[3]); fma2(acc[n2][1], dw, cj1[3]);
                    }
                }
                #pragma unroll
                for (int n2 = 0; n2 < 8; n2++) {
                    acc[n2][0] = add2(acc[n2][0], shfl_xor64(acc[n2][0], 8));
                    acc[n2][1] = add2(acc[n2][1], shfl_xor64(acc[n2][1], 8));
                    acc[n2][0] = add2(acc[n2][0], shfl_xor64(acc[n2][0], 16));
                    acc[n2][1] = add2(acc[n2][1], shfl_xor64(acc[n2][1], 16));
                }
                u64 r0a = acc[0][0], r1a = acc[0][1];
                u64 r0b = acc[1][0], r1b = acc[1][1];
                if (ks == 1) { r0a = acc[2][0]; r1a = acc[2][1];
                               r0b = acc[3][0]; r1b = acc[3][1]; }
                if (ks == 2) { r0a = acc[4][0]; r1a = acc[4][1];
                               r0b = acc[5][0]; r1b = acc[5][1]; }
                if (ks == 3) { r0a = acc[6][0]; r1a = acc[6][1];
                               r0b = acc[7][0]; r1b = acc[7][1]; }
                float a0, a1, a2, a3;
                float* rd = red + (i & 1) * 2048;
                unpk2(r0a, a0, a1); unpk2(r1a, a2, a3);
                *(float4*)(rd + s3 * 256 + (ks * 2) * 32 + jg * 4) =
                    make_float4(a0, a1, a2, a3);
                unpk2(r0b, a0, a1); unpk2(r1b, a2, a3);
                *(float4*)(rd + s3 * 256 + (ks * 2 + 1) * 32 + jg * 4) =
                    make_float4(a0, a1, a2, a3);

                // vectorized qbar: thread owns k = 4*t2 .. 4*t2+3 (LDG.128)
                #pragma unroll
                for (int n2 = 0; n2 < 8; n2++) {
                    ulonglong2 qq =
                        *(const ulonglong2*)(gq + (size_t)n2 * 8192 + 4 * t2);
                    qbs0 = add2(qbs0, qq.x);
                    qbs1 = add2(qbs1, qq.y);
                }
            }
        }
        __syncthreads();
    }

    // ---- flush accumulators ----
    #pragma unroll
    for (int off = 16; off; off >>= 1) {
        ct_comm += __shfl_xor_sync(0xffffffffu, ct_comm, off);
        zsq_acc += __shfl_xor_sync(0xffffffffu, zsq_acc, off);
    }
    if (lane == 0) {
        atomicAdd(&g_comm, ct_comm);
        atomicAdd(&g_qd, zsq_acc + ((w < 8) ? acc_qd : 0.0f));
        if (w < 8) atomicAdd(&g_ne, acc_ne);
    }
    if (w >= 8) {
        float a, b2;
        unpk2(qbs0, a, b2);
        atomicAdd(&g_qbar[c * 1024 + 4 * t2 + 0], a);
        atomicAdd(&g_qbar[c * 1024 + 4 * t2 + 1], b2);
        unpk2(qbs1, a, b2);
        atomicAdd(&g_qbar[c * 1024 + 4 * t2 + 2], a);
        atomicAdd(&g_qbar[c * 1024 + 4 * t2 + 3], b2);
    }

    // ---- last-block finalize (ticket) ----
    __threadfence();
    int* flag = (int*)(sm + OFF_FLG);
    if (t == 0) {
        unsigned int v = atomicAdd(&g_count, 1u);
        flag[0] = (v == (unsigned)(NBLOCKS - 1));
    }
    __syncthreads();
    if (flag[0]) {
        float local = 0.0f;
        #pragma unroll
        for (int it = 0; it < 16; it++) {
            int idx = t + it * THREADS;
            float qb = g_qbar[idx] * (1.0f / 4096.0f);
            local += qb * __logf(fmaf(qb, 1024.0f, 1e-8f));
            g_qbar[idx] = 0.0f;                 // reset for next graph replay
        }
        #pragma unroll
        for (int off = 16; off; off >>= 1)
            local += __shfl_xor_sync(0xffffffffu, local, off);
        if (lane == 0) scr[w] = local;
        __syncthreads();
        if (t == 0) {
            float sr = 0.0f;
            #pragma unroll
            for (int ii = 0; ii < 16; ii++) sr += scr[ii];
            float balance = sr * 0.125f;
            float comm = g_comm * (1.0f / 1048576.0f);
            float mne  = g_ne   * (1.0f / 32768.0f);
            float mqd  = g_qd   * (1.0f / 32768.0f);
            out[O_SC + 0] = comm;
            out[O_SC + 1] = fmaf(mqd, 0.5f, mne) + 6.93147180559945f;
            out[O_SC + 2] = -mne;
            out[O_SC + 3] = balance;
            out[O_SC + 4] = 1.0f;
            g_comm = 0.0f; g_ne = 0.0f; g_qd = 0.0f;
            g_count = 0u;
        }
    }
}

extern "C" void kernel_launch(void* const* d_in, const int* in_sizes, int n_in,
                              void* d_out, int out_size)
{
    const float* z   = (const float*)d_in[0];   // (4,256,32,32) f32
    const float* cbg = (const float*)d_in[1];   // (8,1024,32)  f32
    float* out = (float*)d_out;

    cudaFuncSetAttribute(lgq_main, cudaFuncAttributeMaxDynamicSharedMemorySize,
                         SMEM_BYTES);
    lgq_main<<<NBLOCKS, THREADS, SMEM_BYTES>>>(z, cbg, out);
}